// round 4
// baseline (speedup 1.0000x reference)
#include <cuda_runtime.h>
#include <math.h>
#include <stdint.h>

#define Bsz   2
#define Sseq  2048
#define Dm    1024
#define Hh    16
#define DHd   64
#define BLKs  128
#define NBl   16
#define Mrows (Bsz * Sseq)   // 4096
#define Dff   (4 * Dm)       // 4096

// ---------------- scratch ---------------------------------------------------
__device__ float g_h  [Mrows * Dm];    // permuted tf32
__device__ float g_q  [Mrows * Dm];
__device__ float g_k  [Mrows * Dm];
__device__ float g_v  [Mrows * Dm];
__device__ float g_ctx[Mrows * Dm];    // permuted tf32
__device__ float g_x1 [Mrows * Dm];
__device__ float g_h2 [Mrows * Dm];    // permuted tf32
__device__ float g_ff [Mrows * Dff];   // permuted tf32
__device__ float g_wq [Dm * Dm];       // permuted tf32 weights
__device__ float g_wk [Dm * Dm];
__device__ float g_wv [Dm * Dm];
__device__ float g_wo [Dm * Dm];
__device__ float g_w1 [Dm * Dff];
__device__ float g_w2 [Dff * Dm];

// ---------------- helpers ---------------------------------------------------
__device__ __forceinline__ uint32_t smem_u32(const void* p) {
    uint32_t a;
    asm("{ .reg .u64 t; cvta.to.shared.u64 t, %1; cvt.u32.u64 %0, t; }"
        : "=r"(a) : "l"(p));
    return a;
}
__device__ __forceinline__ float cvt_tf32f(float x) {
    uint32_t r;
    asm("cvt.rna.tf32.f32 %0, %1;" : "=r"(r) : "f"(x));
    return __uint_as_float(r);
}
__device__ __forceinline__ void cpa16(uint32_t dst, const void* src) {
    asm volatile("cp.async.cg.shared.global [%0], [%1], 16;" :: "r"(dst), "l"(src));
}
__device__ __forceinline__ float gelu_exact(float x) {
    return 0.5f * x * (1.0f + erff(x * 0.70710678118654752f));
}

// ---------------- weight prep: W[k][n] -> Wp[k][perm(n)] tf32 ---------------
// perm within each 32-col block: pos = (n%8)*4 + (n/8)%4
__global__ __launch_bounds__(256) void wprep(
    const float* __restrict__ W, float* __restrict__ Wp, int N, int total4)
{
    const int idx = blockIdx.x * 256 + threadIdx.x;
    if (idx >= total4) return;
    const float4 v = reinterpret_cast<const float4*>(W)[idx];
    const int base = idx * 4;
    const int nl0  = (base % N) & 31;
    const int b0   = base - nl0;                 // start of 32-block
    const int p0   = (nl0 & 7) * 4 + ((nl0 >> 3) & 3);
    Wp[b0 + p0 +  0] = cvt_tf32f(v.x);
    Wp[b0 + p0 +  4] = cvt_tf32f(v.y);
    Wp[b0 + p0 +  8] = cvt_tf32f(v.z);
    Wp[b0 + p0 + 12] = cvt_tf32f(v.w);
}

// ---------------- mma.sync tf32 GEMM (prepped operands) ---------------------
// A' permuted [M][K] (pos = (k%4)*8 + (k/4)%8 per 32-blk), W' permuted [K][N].
// EPI: 0 = +bias plain ; 1 = +bias,gelu, OUTPUT PERMUTED ; 2 = +bias,+res plain
#define ASW 36                          // A smem row stride (floats)
#define BSW 136                         // B smem row stride (floats)
#define ASTG_B (128 * ASW * 4)          // 18432
#define BSTG_B (32 * BSW * 4)           // 17408
#define STG_B  (ASTG_B + BSTG_B)        // 35840
#define MMA_SMEM (3 * STG_B)            // 107520

template<int EPI>
__global__ __launch_bounds__(256, 2) void mma_gemm(
    const float* __restrict__ A, const float* __restrict__ W,
    const float* __restrict__ bias, const float* __restrict__ res,
    float* __restrict__ C, int M, int N, int K)
{
    extern __shared__ char smem[];
    const uint32_t sbase = smem_u32(smem);
    const int tid = threadIdx.x;
    const int bm  = blockIdx.y * 128;
    const int bn  = blockIdx.x * 128;
    const int NK  = K >> 5;

    const int arow = tid >> 1;              // 0..127
    const int ah   = tid & 1;
    const int brow = tid >> 3;              // 0..31
    const int bseg = tid & 7;

    const float* Ag0 = A + (size_t)(bm + arow) * K + ah * 16;
    const float* Bg0 = W + (size_t)brow * N + bn + bseg * 16;

    #define ISSUE_CHUNK(kt, st)                                                 \
    {   const uint32_t ab = sbase + (st) * STG_B;                               \
        const float* ag = Ag0 + (size_t)(kt) * 32;                              \
        _Pragma("unroll")                                                       \
        for (int j = 0; j < 4; j++)                                             \
            cpa16(ab + arow * (ASW * 4) + (ah * 4 + j) * 16, ag + j * 4);       \
        const uint32_t bb = ab + ASTG_B;                                        \
        const float* bg = Bg0 + (size_t)(kt) * 32 * N;                          \
        _Pragma("unroll")                                                       \
        for (int j = 0; j < 4; j++)                                             \
            cpa16(bb + brow * (BSW * 4) + (bseg * 4 + j) * 16, bg + j * 4);     \
        asm volatile("cp.async.commit_group;" ::: "memory");                    \
    }

    const int w    = tid >> 5, lane = tid & 31;
    const int wm   = (w >> 2) * 64;
    const int wn   = (w & 3) * 32;
    const int lr   = lane >> 2;
    const int lk   = lane & 3;

    float acc[4][4][4];
    #pragma unroll
    for (int i = 0; i < 4; i++)
        #pragma unroll
        for (int j = 0; j < 4; j++)
            #pragma unroll
            for (int c = 0; c < 4; c++) acc[i][j][c] = 0.f;

    ISSUE_CHUNK(0, 0);
    if (NK > 1) ISSUE_CHUNK(1, 1);

    for (int kt = 0; kt < NK; kt++) {
        const int st = kt % 3;
        if (kt + 1 < NK)
            asm volatile("cp.async.wait_group 1;" ::: "memory");
        else
            asm volatile("cp.async.wait_group 0;" ::: "memory");
        __syncthreads();
        if (kt + 2 < NK) ISSUE_CHUNK(kt + 2, (kt + 2) % 3);

        const float* as = reinterpret_cast<const float*>(smem) + st * (STG_B / 4);
        const float* bs = as + 128 * ASW;

        #pragma unroll
        for (int h = 0; h < 2; h++) {
            // A: 8 x LDS.128 covering sections 2h and 2h+1
            uint4 qa[4][2];
            #pragma unroll
            for (int i = 0; i < 4; i++) {
                const int r0 = wm + i * 16 + lr;
                qa[i][0] = *reinterpret_cast<const uint4*>(as + r0 * ASW + lk * 8 + 4 * h);
                qa[i][1] = *reinterpret_cast<const uint4*>(as + (r0 + 8) * ASW + lk * 8 + 4 * h);
            }
            #pragma unroll
            for (int s2 = 0; s2 < 2; s2++) {
                const int k0 = (2 * h + s2) * 8 + lk;
                const uint4 b0 = *reinterpret_cast<const uint4*>(bs + k0 * BSW + wn + lr * 4);
                const uint4 b1 = *reinterpret_cast<const uint4*>(bs + (k0 + 4) * BSW + wn + lr * 4);
                const uint32_t bf0[4] = {b0.x, b0.y, b0.z, b0.w};
                const uint32_t bf1[4] = {b1.x, b1.y, b1.z, b1.w};
                #pragma unroll
                for (int i = 0; i < 4; i++) {
                    const uint32_t a0 = s2 ? qa[i][0].z : qa[i][0].x;
                    const uint32_t a1 = s2 ? qa[i][1].z : qa[i][1].x;
                    const uint32_t a2 = s2 ? qa[i][0].w : qa[i][0].y;
                    const uint32_t a3 = s2 ? qa[i][1].w : qa[i][1].y;
                    #pragma unroll
                    for (int j = 0; j < 4; j++)
                        asm volatile(
                            "mma.sync.aligned.m16n8k8.row.col.f32.tf32.tf32.f32 "
                            "{%0,%1,%2,%3}, {%4,%5,%6,%7}, {%8,%9}, {%0,%1,%2,%3};"
                            : "+f"(acc[i][j][0]), "+f"(acc[i][j][1]),
                              "+f"(acc[i][j][2]), "+f"(acc[i][j][3])
                            : "r"(a0), "r"(a1), "r"(a2), "r"(a3),
                              "r"(bf0[j]), "r"(bf1[j]));
                }
            }
        }
    }
    #undef ISSUE_CHUNK

    // epilogue
    #pragma unroll
    for (int i = 0; i < 4; i++) {
        #pragma unroll
        for (int j = 0; j < 4; j++) {
            const int row0 = bm + wm + i * 16 + lr;
            const int col  = bn + wn + j * 8 + lk * 2;
            #pragma unroll
            for (int hrow = 0; hrow < 2; hrow++) {
                const int row = row0 + hrow * 8;
                float ox = acc[i][j][hrow * 2 + 0] + bias[col + 0];
                float oy = acc[i][j][hrow * 2 + 1] + bias[col + 1];
                if (EPI == 1) {
                    ox = gelu_exact(ox); oy = gelu_exact(oy);
                    // permuted tf32 output (consumed as A operand downstream)
                    const int nl = col & 31;
                    const int p0 = (nl & 3) * 8 + (nl >> 2);
                    float* dst = C + (size_t)row * N + (col - nl);
                    dst[p0]     = cvt_tf32f(ox);
                    dst[p0 + 8] = cvt_tf32f(oy);
                } else {
                    if (EPI == 2) {
                        const float2 r2 = *reinterpret_cast<const float2*>(
                            res + (size_t)row * N + col);
                        ox += r2.x; oy += r2.y;
                    }
                    float2 o; o.x = ox; o.y = oy;
                    *reinterpret_cast<float2*>(C + (size_t)row * N + col) = o;
                }
            }
        }
    }
}

// ---------------- LayerNorm (PERM: write permuted tf32) ---------------------
template<int PERM>
__global__ __launch_bounds__(256) void ln_kernel(
    const float* __restrict__ x, const float* __restrict__ g,
    const float* __restrict__ b, float* __restrict__ out)
{
    const int row = blockIdx.x;
    const int t   = threadIdx.x;
    const float4 v = reinterpret_cast<const float4*>(x + (size_t)row * Dm)[t];

    float s  = v.x + v.y + v.z + v.w;
    float s2 = v.x * v.x + v.y * v.y + v.z * v.z + v.w * v.w;

    __shared__ float red[16];
    #pragma unroll
    for (int o = 16; o; o >>= 1) {
        s  += __shfl_xor_sync(0xffffffffu, s,  o);
        s2 += __shfl_xor_sync(0xffffffffu, s2, o);
    }
    const int w = t >> 5, l = t & 31;
    if (l == 0) { red[w] = s; red[w + 8] = s2; }
    __syncthreads();
    if (w == 0) {
        float a  = (l < 8) ? red[l]     : 0.f;
        float a2 = (l < 8) ? red[l + 8] : 0.f;
        #pragma unroll
        for (int o = 4; o; o >>= 1) {
            a  += __shfl_xor_sync(0xffffffffu, a,  o);
            a2 += __shfl_xor_sync(0xffffffffu, a2, o);
        }
        if (l == 0) { red[0] = a; red[1] = a2; }
    }
    __syncthreads();

    const float mean = red[0] * (1.f / Dm);
    const float var  = red[1] * (1.f / Dm) - mean * mean;
    const float rs   = rsqrtf(var + 1e-5f);

    const float4 gg = reinterpret_cast<const float4*>(g)[t];
    const float4 bb = reinterpret_cast<const float4*>(b)[t];
    float o0 = (v.x - mean) * rs * gg.x + bb.x;
    float o1 = (v.y - mean) * rs * gg.y + bb.y;
    float o2 = (v.z - mean) * rs * gg.z + bb.z;
    float o3 = (v.w - mean) * rs * gg.w + bb.w;

    if (PERM) {
        // k = 4t..4t+3 ; block = (t>>3)*32 ; pos = i*8 + (t&7)
        float* dst = out + (size_t)row * Dm + (t >> 3) * 32 + (t & 7);
        dst[0]  = cvt_tf32f(o0);
        dst[8]  = cvt_tf32f(o1);
        dst[16] = cvt_tf32f(o2);
        dst[24] = cvt_tf32f(o3);
    } else {
        float4 o4; o4.x = o0; o4.y = o1; o4.z = o2; o4.w = o3;
        reinterpret_cast<float4*>(out + (size_t)row * Dm)[t] = o4;
    }
}

// ---------------- block-sparse flash attention ------------------------------
#define SPAD 130

__global__ __launch_bounds__(256) void attn_kernel(
    const float* __restrict__ q, const float* __restrict__ k,
    const float* __restrict__ v, const int* __restrict__ layout,
    float* __restrict__ ctx)
{
    extern __shared__ float sm[];
    float* sKV  = sm;
    float* sS   = sm + 128 * 64;
    float* sRed = sS + 128 * SPAD;

    const int ib  = blockIdx.x;
    const int hh  = blockIdx.y;
    const int bb  = blockIdx.z;
    const int tid = threadIdx.x;
    const int r    = tid >> 1;
    const int half = tid & 1;

    const size_t qbase = ((size_t)(bb * Sseq + ib * BLKs)) * Dm + hh * DHd;

    #pragma unroll
    for (int f = tid; f < 2048; f += 256) {
        const int row = f >> 4, c = (f & 15) << 2;
        *reinterpret_cast<float4*>(sKV + row * 64 + c) =
            *reinterpret_cast<const float4*>(q + qbase + (size_t)row * Dm + c);
    }
    __syncthreads();
    float qreg[64];
    #pragma unroll
    for (int c = 0; c < 64; c += 4)
        *reinterpret_cast<float4*>(qreg + c) = *reinterpret_cast<float4*>(sKV + r * 64 + c);

    float m = -1e30f, l = 0.f;
    float cacc[32];
    #pragma unroll
    for (int d = 0; d < 32; d++) cacc[d] = 0.f;
    const float scale = 0.125f;

    for (int j = 0; j <= ib; j++) {
        if (!layout[(hh * NBl + ib) * NBl + j]) continue;

        __syncthreads();
        const size_t kbase = ((size_t)(bb * Sseq + j * BLKs)) * Dm + hh * DHd;
        #pragma unroll
        for (int f = tid; f < 2048; f += 256) {
            const int row = f >> 4, c = (f & 15) << 2;
            *reinterpret_cast<float4*>(sKV + row * 64 + c) =
                *reinterpret_cast<const float4*>(k + kbase + (size_t)row * Dm + c);
        }
        __syncthreads();

        const int t0 = half * 64;
        float lmax = -1e30f;
        for (int tl = 0; tl < 64; tl++) {
            const int t = t0 + tl;
            float s;
            if (j < ib || t <= r) {
                float dot = 0.f;
                const float* kr = sKV + t * 64;
                #pragma unroll
                for (int d = 0; d < 64; d++) dot = fmaf(qreg[d], kr[d], dot);
                s = dot * scale;
            } else {
                s = -1e9f;
            }
            sS[r * SPAD + half * 65 + tl] = s;
            lmax = fmaxf(lmax, s);
        }
        sRed[r * 2 + half] = lmax;
        __syncthreads();

        #pragma unroll
        for (int f = tid; f < 2048; f += 256) {
            const int row = f >> 4, c = (f & 15) << 2;
            *reinterpret_cast<float4*>(sKV + row * 64 + c) =
                *reinterpret_cast<const float4*>(v + kbase + (size_t)row * Dm + c);
        }

        const float mb   = fmaxf(sRed[r * 2], sRed[r * 2 + 1]);
        const float mnew = fmaxf(m, mb);
        const float corr = __expf(m - mnew);
        float lsum = 0.f;
        for (int tl = 0; tl < 64; tl++) {
            const int idx = r * SPAD + half * 65 + tl;
            const float p = __expf(sS[idx] - mnew);
            sS[idx] = p;
            lsum += p;
        }
        sRed[256 + r * 2 + half] = lsum;
        __syncthreads();

        l = l * corr + sRed[256 + r * 2] + sRed[256 + r * 2 + 1];
        #pragma unroll
        for (int d = 0; d < 32; d++) cacc[d] *= corr;
        for (int t = 0; t < 128; t++) {
            const float p = sS[r * SPAD + t + (t >> 6)];
            const float* vr = sKV + t * 64 + half * 32;
            #pragma unroll
            for (int d = 0; d < 32; d++) cacc[d] = fmaf(p, vr[d], cacc[d]);
        }
        m = mnew;
    }

    // permuted tf32 output: column block base = hh*64 + half*32 (32-aligned)
    const float inv = 1.f / l;
    float* dst = ctx + ((size_t)(bb * Sseq + ib * BLKs + r)) * Dm + hh * DHd + half * 32;
    #pragma unroll
    for (int d = 0; d < 32; d++) {
        const int pos = (d & 3) * 8 + (d >> 2);
        dst[pos] = cvt_tf32f(cacc[d] * inv);
    }
}

#define ATTN_SMEM (128 * 64 * 4 + 128 * SPAD * 4 + 512 * 4)

// ---------------------------------------------------------------------------
extern "C" void kernel_launch(void* const* d_in, const int* in_sizes, int n_in,
                              void* d_out, int out_size)
{
    (void)in_sizes; (void)n_in; (void)out_size;
    const float* x     = (const float*)d_in[0];
    const float* ln1_g = (const float*)d_in[1];
    const float* ln1_b = (const float*)d_in[2];
    const float* Wq    = (const float*)d_in[3];
    const float* bq    = (const float*)d_in[4];
    const float* Wk    = (const float*)d_in[5];
    const float* bk    = (const float*)d_in[6];
    const float* Wv    = (const float*)d_in[7];
    const float* bv    = (const float*)d_in[8];
    const float* Wo    = (const float*)d_in[9];
    const float* bo    = (const float*)d_in[10];
    const float* ln2_g = (const float*)d_in[11];
    const float* ln2_b = (const float*)d_in[12];
    const float* W1    = (const float*)d_in[13];
    const float* b1    = (const float*)d_in[14];
    const float* W2    = (const float*)d_in[15];
    const float* b2    = (const float*)d_in[16];
    const int*   lay   = (const int*)d_in[17];
    float* out = (float*)d_out;

    float *h, *q, *k, *v, *ctx, *x1, *h2, *ff;
    float *wq, *wk, *wv, *wo, *w1, *w2;
    cudaGetSymbolAddress((void**)&h,   g_h);
    cudaGetSymbolAddress((void**)&q,   g_q);
    cudaGetSymbolAddress((void**)&k,   g_k);
    cudaGetSymbolAddress((void**)&v,   g_v);
    cudaGetSymbolAddress((void**)&ctx, g_ctx);
    cudaGetSymbolAddress((void**)&x1,  g_x1);
    cudaGetSymbolAddress((void**)&h2,  g_h2);
    cudaGetSymbolAddress((void**)&ff,  g_ff);
    cudaGetSymbolAddress((void**)&wq,  g_wq);
    cudaGetSymbolAddress((void**)&wk,  g_wk);
    cudaGetSymbolAddress((void**)&wv,  g_wv);
    cudaGetSymbolAddress((void**)&wo,  g_wo);
    cudaGetSymbolAddress((void**)&w1,  g_w1);
    cudaGetSymbolAddress((void**)&w2,  g_w2);

    cudaFuncSetAttribute(attn_kernel,
                         cudaFuncAttributeMaxDynamicSharedMemorySize, ATTN_SMEM);
    cudaFuncSetAttribute(mma_gemm<0>,
                         cudaFuncAttributeMaxDynamicSharedMemorySize, MMA_SMEM);
    cudaFuncSetAttribute(mma_gemm<1>,
                         cudaFuncAttributeMaxDynamicSharedMemorySize, MMA_SMEM);
    cudaFuncSetAttribute(mma_gemm<2>,
                         cudaFuncAttributeMaxDynamicSharedMemorySize, MMA_SMEM);

    // 0) weight prep (permute + tf32)
    wprep<<<(Dm * Dm / 4 + 255) / 256, 256>>>(Wq, wq, Dm, Dm * Dm / 4);
    wprep<<<(Dm * Dm / 4 + 255) / 256, 256>>>(Wk, wk, Dm, Dm * Dm / 4);
    wprep<<<(Dm * Dm / 4 + 255) / 256, 256>>>(Wv, wv, Dm, Dm * Dm / 4);
    wprep<<<(Dm * Dm / 4 + 255) / 256, 256>>>(Wo, wo, Dm, Dm * Dm / 4);
    wprep<<<(Dm * Dff / 4 + 255) / 256, 256>>>(W1, w1, Dff, Dm * Dff / 4);
    wprep<<<(Dff * Dm / 4 + 255) / 256, 256>>>(W2, w2, Dm, Dff * Dm / 4);

    // 1) ln1 -> permuted h
    ln_kernel<1><<<Mrows, 256>>>(x, ln1_g, ln1_b, h);

    // 2) QKV projections (plain outputs)
    dim3 g1(Dm / 128, Mrows / 128);
    mma_gemm<0><<<g1, 256, MMA_SMEM>>>(h, wq, bq, nullptr, q, Mrows, Dm, Dm);
    mma_gemm<0><<<g1, 256, MMA_SMEM>>>(h, wk, bk, nullptr, k, Mrows, Dm, Dm);
    mma_gemm<0><<<g1, 256, MMA_SMEM>>>(h, wv, bv, nullptr, v, Mrows, Dm, Dm);

    // 3) block-sparse attention -> permuted ctx
    attn_kernel<<<dim3(NBl, Hh, Bsz), 256, ATTN_SMEM>>>(q, k, v, lay, ctx);

    // 4) output projection + residual (plain x1)
    mma_gemm<2><<<g1, 256, MMA_SMEM>>>(ctx, wo, bo, x, x1, Mrows, Dm, Dm);

    // 5) ln2 -> permuted h2
    ln_kernel<1><<<Mrows, 256>>>(x1, ln2_g, ln2_b, h2);

    // 6) MLP: gelu output permuted, final plain
    dim3 g2(Dff / 128, Mrows / 128);
    mma_gemm<1><<<g2, 256, MMA_SMEM>>>(h2, w1, b1, nullptr, ff, Mrows, Dff, Dm);
    mma_gemm<2><<<g1, 256, MMA_SMEM>>>(ff, w2, b2, x1, out, Mrows, Dm, Dff);
}

// round 6
// speedup vs baseline: 1.1103x; 1.1103x over previous
#include <cuda_runtime.h>
#include <math.h>
#include <stdint.h>

#define Bsz   2
#define Sseq  2048
#define Dm    1024
#define Hh    16
#define DHd   64
#define BLKs  128
#define NBl   16
#define Mrows (Bsz * Sseq)   // 4096
#define Dff   (4 * Dm)       // 4096
#define QKV3  (3 * Dm)       // 3072

// ---------------- scratch ---------------------------------------------------
__device__ float g_h   [Mrows * Dm];    // tf32-rounded
__device__ float g_qkv [Mrows * QKV3];
__device__ float g_ctx [Mrows * Dm];    // tf32-rounded
__device__ float g_x1  [Mrows * Dm];
__device__ float g_h2  [Mrows * Dm];    // tf32-rounded
__device__ float g_ff  [Mrows * Dff];   // tf32-rounded
__device__ float g_wqkv[Dm * QKV3];     // tf32-rounded weights
__device__ float g_wo  [Dm * Dm];
__device__ float g_w1  [Dm * Dff];
__device__ float g_w2  [Dff * Dm];
__device__ float g_bqkv[QKV3];

// ---------------- helpers ---------------------------------------------------
__device__ __forceinline__ uint32_t smem_u32(const void* p) {
    uint32_t a;
    asm("{ .reg .u64 t; cvta.to.shared.u64 t, %1; cvt.u32.u64 %0, t; }"
        : "=r"(a) : "l"(p));
    return a;
}
__device__ __forceinline__ float cvt_tf32f(float x) {
    uint32_t r;
    asm("cvt.rna.tf32.f32 %0, %1;" : "=r"(r) : "f"(x));
    return __uint_as_float(r);
}
__device__ __forceinline__ void cpa16(uint32_t dst, const void* src) {
    asm volatile("cp.async.cg.shared.global [%0], [%1], 16;" :: "r"(dst), "l"(src));
}
__device__ __forceinline__ float gelu_exact(float x) {
    return 0.5f * x * (1.0f + erff(x * 0.70710678118654752f));
}

// ---------------- weight prep: rounded copy (optional column offset) --------
__global__ __launch_bounds__(256) void wprep(
    const float* __restrict__ W, float* __restrict__ Wp,
    int srcN, int dstN, int colOff, int total4)
{
    const int idx = blockIdx.x * 256 + threadIdx.x;
    if (idx >= total4) return;
    const float4 v = reinterpret_cast<const float4*>(W)[idx];
    const int srcN4 = srcN >> 2;
    const int k  = idx / srcN4;
    const int c4 = idx - k * srcN4;
    float4 o;
    o.x = cvt_tf32f(v.x); o.y = cvt_tf32f(v.y);
    o.z = cvt_tf32f(v.z); o.w = cvt_tf32f(v.w);
    *reinterpret_cast<float4*>(Wp + (size_t)k * dstN + colOff + c4 * 4) = o;
}

__global__ __launch_bounds__(256) void bprep(
    const float* __restrict__ bq, const float* __restrict__ bk,
    const float* __restrict__ bv, float* __restrict__ dst)
{
    const int i = blockIdx.x * 256 + threadIdx.x;
    if (i >= QKV3) return;
    dst[i] = (i < Dm) ? bq[i] : (i < 2 * Dm) ? bk[i - Dm] : bv[i - 2 * Dm];
}

// ---------------- mma.sync tf32 GEMM (pre-rounded operands) -----------------
// EPI: 0 = +bias ; 1 = +bias, gelu, tf32-round out ; 2 = +bias, +res
#define APADW 36
#define BPADW 136
#define ASTG_B (128 * APADW * 4)          // 18432
#define BSTG_B (32 * BPADW * 4)           // 17408
#define STG_B  (ASTG_B + BSTG_B)          // 35840
#define MMA_SMEM (3 * STG_B)              // 107520

template<int EPI>
__global__ __launch_bounds__(256, 2) void mma_gemm(
    const float* __restrict__ A, const float* __restrict__ W,
    const float* __restrict__ bias, const float* __restrict__ res,
    float* __restrict__ C, int M, int N, int K)
{
    extern __shared__ char smem[];
    const uint32_t sbase = smem_u32(smem);
    const int tid = threadIdx.x;
    const int bm  = blockIdx.y * 128;
    const int bn  = blockIdx.x * 128;
    const int NK  = K >> 5;

    const int arow = tid >> 1;              // 0..127
    const int ah   = tid & 1;
    const int brow = tid >> 3;              // 0..31
    const int bseg = tid & 7;

    const float* Ag0 = A + (size_t)(bm + arow) * K + ah * 16;
    const float* Bg0 = W + (size_t)brow * N + bn + bseg * 16;

    #define ISSUE_CHUNK(kt, st)                                                 \
    {   const uint32_t ab = sbase + (st) * STG_B;                               \
        const float* ag = Ag0 + (size_t)(kt) * 32;                              \
        _Pragma("unroll")                                                       \
        for (int j = 0; j < 4; j++)                                             \
            cpa16(ab + arow * (APADW * 4) + (ah * 4 + j) * 16, ag + j * 4);     \
        const uint32_t bb = ab + ASTG_B;                                        \
        const float* bg = Bg0 + (size_t)(kt) * 32 * N;                          \
        _Pragma("unroll")                                                       \
        for (int j = 0; j < 4; j++)                                             \
            cpa16(bb + brow * (BPADW * 4) + (bseg * 4 + j) * 16, bg + j * 4);   \
        asm volatile("cp.async.commit_group;" ::: "memory");                    \
    }

    const int w    = tid >> 5, lane = tid & 31;
    const int wm   = (w >> 2) * 64;
    const int wn   = (w & 3) * 32;
    const int lr   = lane >> 2;
    const int lk   = lane & 3;

    float acc[4][4][4];
    #pragma unroll
    for (int i = 0; i < 4; i++)
        #pragma unroll
        for (int j = 0; j < 4; j++)
            #pragma unroll
            for (int c = 0; c < 4; c++) acc[i][j][c] = 0.f;

    ISSUE_CHUNK(0, 0);
    if (NK > 1) ISSUE_CHUNK(1, 1);

    for (int kt = 0; kt < NK; kt++) {
        const int st = kt % 3;
        if (kt + 1 < NK)
            asm volatile("cp.async.wait_group 1;" ::: "memory");
        else
            asm volatile("cp.async.wait_group 0;" ::: "memory");
        __syncthreads();
        if (kt + 2 < NK) ISSUE_CHUNK(kt + 2, (kt + 2) % 3);

        const float* as = reinterpret_cast<const float*>(smem) + st * (STG_B / 4);
        const float* bs = as + 128 * APADW;

        #pragma unroll
        for (int s = 0; s < 4; s++) {
            const int k0 = s * 8 + lk;
            uint32_t af[4][4], bf[4][2];
            #pragma unroll
            for (int i = 0; i < 4; i++) {
                const int r = wm + i * 16 + lr;
                af[i][0] = __float_as_uint(as[r * APADW + k0]);
                af[i][1] = __float_as_uint(as[(r + 8) * APADW + k0]);
                af[i][2] = __float_as_uint(as[r * APADW + k0 + 4]);
                af[i][3] = __float_as_uint(as[(r + 8) * APADW + k0 + 4]);
            }
            #pragma unroll
            for (int j = 0; j < 4; j++) {
                const int n = wn + j * 8 + lr;
                bf[j][0] = __float_as_uint(bs[k0 * BPADW + n]);
                bf[j][1] = __float_as_uint(bs[(k0 + 4) * BPADW + n]);
            }
            #pragma unroll
            for (int i = 0; i < 4; i++)
                #pragma unroll
                for (int j = 0; j < 4; j++)
                    asm volatile(
                        "mma.sync.aligned.m16n8k8.row.col.f32.tf32.tf32.f32 "
                        "{%0,%1,%2,%3}, {%4,%5,%6,%7}, {%8,%9}, {%0,%1,%2,%3};"
                        : "+f"(acc[i][j][0]), "+f"(acc[i][j][1]),
                          "+f"(acc[i][j][2]), "+f"(acc[i][j][3])
                        : "r"(af[i][0]), "r"(af[i][1]), "r"(af[i][2]), "r"(af[i][3]),
                          "r"(bf[j][0]), "r"(bf[j][1]));
        }
    }
    #undef ISSUE_CHUNK

    // epilogue
    #pragma unroll
    for (int i = 0; i < 4; i++) {
        #pragma unroll
        for (int j = 0; j < 4; j++) {
            const int row0 = bm + wm + i * 16 + lr;
            const int col  = bn + wn + j * 8 + lk * 2;
            #pragma unroll
            for (int hrow = 0; hrow < 2; hrow++) {
                const int row = row0 + hrow * 8;
                float ox = acc[i][j][hrow * 2 + 0] + bias[col + 0];
                float oy = acc[i][j][hrow * 2 + 1] + bias[col + 1];
                if (EPI == 1) {
                    ox = cvt_tf32f(gelu_exact(ox));
                    oy = cvt_tf32f(gelu_exact(oy));
                }
                if (EPI == 2) {
                    const float2 r2 = *reinterpret_cast<const float2*>(
                        res + (size_t)row * N + col);
                    ox += r2.x; oy += r2.y;
                }
                float2 o; o.x = ox; o.y = oy;
                *reinterpret_cast<float2*>(C + (size_t)row * N + col) = o;
            }
        }
    }
}

// ---------------- LayerNorm (tf32-rounded output) ---------------------------
__global__ __launch_bounds__(256) void ln_kernel(
    const float* __restrict__ x, const float* __restrict__ g,
    const float* __restrict__ b, float* __restrict__ out)
{
    const int row = blockIdx.x;
    const int t   = threadIdx.x;
    const float4 v = reinterpret_cast<const float4*>(x + (size_t)row * Dm)[t];

    float s  = v.x + v.y + v.z + v.w;
    float s2 = v.x * v.x + v.y * v.y + v.z * v.z + v.w * v.w;

    __shared__ float red[16];
    #pragma unroll
    for (int o = 16; o; o >>= 1) {
        s  += __shfl_xor_sync(0xffffffffu, s,  o);
        s2 += __shfl_xor_sync(0xffffffffu, s2, o);
    }
    const int w = t >> 5, l = t & 31;
    if (l == 0) { red[w] = s; red[w + 8] = s2; }
    __syncthreads();
    if (w == 0) {
        float a  = (l < 8) ? red[l]     : 0.f;
        float a2 = (l < 8) ? red[l + 8] : 0.f;
        #pragma unroll
        for (int o = 4; o; o >>= 1) {
            a  += __shfl_xor_sync(0xffffffffu, a,  o);
            a2 += __shfl_xor_sync(0xffffffffu, a2, o);
        }
        if (l == 0) { red[0] = a; red[1] = a2; }
    }
    __syncthreads();

    const float mean = red[0] * (1.f / Dm);
    const float var  = red[1] * (1.f / Dm) - mean * mean;
    const float rs   = rsqrtf(var + 1e-5f);

    const float4 gg = reinterpret_cast<const float4*>(g)[t];
    const float4 bb = reinterpret_cast<const float4*>(b)[t];
    float4 o4;
    o4.x = cvt_tf32f((v.x - mean) * rs * gg.x + bb.x);
    o4.y = cvt_tf32f((v.y - mean) * rs * gg.y + bb.y);
    o4.z = cvt_tf32f((v.z - mean) * rs * gg.z + bb.z);
    o4.w = cvt_tf32f((v.w - mean) * rs * gg.w + bb.w);
    reinterpret_cast<float4*>(out + (size_t)row * Dm)[t] = o4;
}

// ---------------- block-sparse flash attention (packed qkv input) -----------
#define SPAD 130

__global__ __launch_bounds__(256) void attn_kernel(
    const float* __restrict__ qkv, const int* __restrict__ layout,
    float* __restrict__ ctx)
{
    extern __shared__ float sm[];
    float* sKV  = sm;
    float* sS   = sm + 128 * 64;
    float* sRed = sS + 128 * SPAD;

    const int ib  = blockIdx.x;
    const int hh  = blockIdx.y;
    const int bb  = blockIdx.z;
    const int tid = threadIdx.x;
    const int r    = tid >> 1;
    const int half = tid & 1;

    const size_t qbase = ((size_t)(bb * Sseq + ib * BLKs)) * QKV3 + hh * DHd;
    const float* kptr = qkv + Dm;
    const float* vptr = qkv + 2 * Dm;

    #pragma unroll
    for (int f = tid; f < 2048; f += 256) {
        const int row = f >> 4, c = (f & 15) << 2;
        *reinterpret_cast<float4*>(sKV + row * 64 + c) =
            *reinterpret_cast<const float4*>(qkv + qbase + (size_t)row * QKV3 + c);
    }
    __syncthreads();
    float qreg[64];
    #pragma unroll
    for (int c = 0; c < 64; c += 4)
        *reinterpret_cast<float4*>(qreg + c) = *reinterpret_cast<float4*>(sKV + r * 64 + c);

    float m = -1e30f, l = 0.f;
    float cacc[32];
    #pragma unroll
    for (int d = 0; d < 32; d++) cacc[d] = 0.f;
    const float scale = 0.125f;

    for (int j = 0; j <= ib; j++) {
        if (!layout[(hh * NBl + ib) * NBl + j]) continue;

        __syncthreads();
        const size_t kbase = ((size_t)(bb * Sseq + j * BLKs)) * QKV3 + hh * DHd;
        #pragma unroll
        for (int f = tid; f < 2048; f += 256) {
            const int row = f >> 4, c = (f & 15) << 2;
            *reinterpret_cast<float4*>(sKV + row * 64 + c) =
                *reinterpret_cast<const float4*>(kptr + kbase + (size_t)row * QKV3 + c);
        }
        __syncthreads();

        const int t0 = half * 64;
        float lmax = -1e30f;
        for (int tl = 0; tl < 64; tl++) {
            const int t = t0 + tl;
            float s;
            if (j < ib || t <= r) {
                float dot = 0.f;
                const float* kr = sKV + t * 64;
                #pragma unroll
                for (int d = 0; d < 64; d++) dot = fmaf(qreg[d], kr[d], dot);
                s = dot * scale;
            } else {
                s = -1e9f;
            }
            sS[r * SPAD + half * 65 + tl] = s;
            lmax = fmaxf(lmax, s);
        }
        sRed[r * 2 + half] = lmax;
        __syncthreads();

        #pragma unroll
        for (int f = tid; f < 2048; f += 256) {
            const int row = f >> 4, c = (f & 15) << 2;
            *reinterpret_cast<float4*>(sKV + row * 64 + c) =
                *reinterpret_cast<const float4*>(vptr + kbase + (size_t)row * QKV3 + c);
        }

        const float mb   = fmaxf(sRed[r * 2], sRed[r * 2 + 1]);
        const float mnew = fmaxf(m, mb);
        const float corr = __expf(m - mnew);
        float lsum = 0.f;
        for (int tl = 0; tl < 64; tl++) {
            const int idx = r * SPAD + half * 65 + tl;
            const float p = __expf(sS[idx] - mnew);
            sS[idx] = p;
            lsum += p;
        }
        sRed[256 + r * 2 + half] = lsum;
        __syncthreads();

        l = l * corr + sRed[256 + r * 2] + sRed[256 + r * 2 + 1];
        #pragma unroll
        for (int d = 0; d < 32; d++) cacc[d] *= corr;
        for (int t = 0; t < 128; t++) {
            const float p = sS[r * SPAD + t + (t >> 6)];
            const float* vr = sKV + t * 64 + half * 32;
            #pragma unroll
            for (int d = 0; d < 32; d++) cacc[d] = fmaf(p, vr[d], cacc[d]);
        }
        m = mnew;
    }

    const float inv = 1.f / l;
    float* dst = ctx + ((size_t)(bb * Sseq + ib * BLKs + r)) * Dm + hh * DHd + half * 32;
    #pragma unroll
    for (int d = 0; d < 32; d += 4) {
        float4 o;
        o.x = cvt_tf32f(cacc[d + 0] * inv);
        o.y = cvt_tf32f(cacc[d + 1] * inv);
        o.z = cvt_tf32f(cacc[d + 2] * inv);
        o.w = cvt_tf32f(cacc[d + 3] * inv);
        *reinterpret_cast<float4*>(dst + d) = o;
    }
}

#define ATTN_SMEM (128 * 64 * 4 + 128 * SPAD * 4 + 512 * 4)

// ---------------------------------------------------------------------------
extern "C" void kernel_launch(void* const* d_in, const int* in_sizes, int n_in,
                              void* d_out, int out_size)
{
    (void)in_sizes; (void)n_in; (void)out_size;
    const float* x     = (const float*)d_in[0];
    const float* ln1_g = (const float*)d_in[1];
    const float* ln1_b = (const float*)d_in[2];
    const float* Wq    = (const float*)d_in[3];
    const float* bq    = (const float*)d_in[4];
    const float* Wk    = (const float*)d_in[5];
    const float* bk    = (const float*)d_in[6];
    const float* Wv    = (const float*)d_in[7];
    const float* bv    = (const float*)d_in[8];
    const float* Wo    = (const float*)d_in[9];
    const float* bo    = (const float*)d_in[10];
    const float* ln2_g = (const float*)d_in[11];
    const float* ln2_b = (const float*)d_in[12];
    const float* W1    = (const float*)d_in[13];
    const float* b1    = (const float*)d_in[14];
    const float* W2    = (const float*)d_in[15];
    const float* b2    = (const float*)d_in[16];
    const int*   lay   = (const int*)d_in[17];
    float* out = (float*)d_out;

    float *h, *qkv, *ctx, *x1, *h2, *ff;
    float *wqkv, *wo, *w1, *w2, *bqkv;
    cudaGetSymbolAddress((void**)&h,    g_h);
    cudaGetSymbolAddress((void**)&qkv,  g_qkv);
    cudaGetSymbolAddress((void**)&ctx,  g_ctx);
    cudaGetSymbolAddress((void**)&x1,   g_x1);
    cudaGetSymbolAddress((void**)&h2,   g_h2);
    cudaGetSymbolAddress((void**)&ff,   g_ff);
    cudaGetSymbolAddress((void**)&wqkv, g_wqkv);
    cudaGetSymbolAddress((void**)&wo,   g_wo);
    cudaGetSymbolAddress((void**)&w1,   g_w1);
    cudaGetSymbolAddress((void**)&w2,   g_w2);
    cudaGetSymbolAddress((void**)&bqkv, g_bqkv);

    cudaFuncSetAttribute(attn_kernel,
                         cudaFuncAttributeMaxDynamicSharedMemorySize, ATTN_SMEM);
    cudaFuncSetAttribute(mma_gemm<0>,
                         cudaFuncAttributeMaxDynamicSharedMemorySize, MMA_SMEM);
    cudaFuncSetAttribute(mma_gemm<1>,
                         cudaFuncAttributeMaxDynamicSharedMemorySize, MMA_SMEM);
    cudaFuncSetAttribute(mma_gemm<2>,
                         cudaFuncAttributeMaxDynamicSharedMemorySize, MMA_SMEM);

    // 0) weight prep (tf32 rounding; QKV concatenated)
    const int nDmDm = Dm * Dm / 4;
    wprep<<<(nDmDm + 255) / 256, 256>>>(Wq, wqkv, Dm, QKV3, 0,      nDmDm);
    wprep<<<(nDmDm + 255) / 256, 256>>>(Wk, wqkv, Dm, QKV3, Dm,     nDmDm);
    wprep<<<(nDmDm + 255) / 256, 256>>>(Wv, wqkv, Dm, QKV3, 2 * Dm, nDmDm);
    wprep<<<(nDmDm + 255) / 256, 256>>>(Wo, wo,  Dm,  Dm,  0, nDmDm);
    wprep<<<(Dm * Dff / 4 + 255) / 256, 256>>>(W1, w1, Dff, Dff, 0, Dm * Dff / 4);
    wprep<<<(Dff * Dm / 4 + 255) / 256, 256>>>(W2, w2, Dm,  Dm,  0, Dff * Dm / 4);
    bprep<<<(QKV3 + 255) / 256, 256>>>(bq, bk, bv, bqkv);

    // 1) ln1 -> rounded h
    ln_kernel<<<Mrows, 256>>>(x, ln1_g, ln1_b, h);

    // 2) fused QKV projection
    mma_gemm<0><<<dim3(QKV3 / 128, Mrows / 128), 256, MMA_SMEM>>>(
        h, wqkv, bqkv, nullptr, qkv, Mrows, QKV3, Dm);

    // 3) block-sparse attention -> rounded ctx
    attn_kernel<<<dim3(NBl, Hh, Bsz), 256, ATTN_SMEM>>>(qkv, lay, ctx);

    // 4) output projection + residual
    dim3 g1(Dm / 128, Mrows / 128);
    mma_gemm<2><<<g1, 256, MMA_SMEM>>>(ctx, wo, bo, x, x1, Mrows, Dm, Dm);

    // 5) ln2 -> rounded h2
    ln_kernel<<<Mrows, 256>>>(x1, ln2_g, ln2_b, h2);

    // 6) MLP
    dim3 g2(Dff / 128, Mrows / 128);
    mma_gemm<1><<<g2, 256, MMA_SMEM>>>(h2, w1, b1, nullptr, ff, Mrows, Dff, Dm);
    mma_gemm<2><<<g1, 256, MMA_SMEM>>>(ff, w2, b2, x1, out, Mrows, Dm, Dff);
}

// round 8
// speedup vs baseline: 1.7892x; 1.6115x over previous
#include <cuda_runtime.h>
#include <cuda_fp16.h>
#include <math.h>
#include <stdint.h>

#define Bsz   2
#define Sseq  2048
#define Dm    1024
#define Hh    16
#define DHd   64
#define BLKs  128
#define NBl   16
#define Mrows (Bsz * Sseq)   // 4096
#define Dff   (4 * Dm)       // 4096
#define QKV3  (3 * Dm)       // 3072

// ---------------- scratch ---------------------------------------------------
__device__ __half g_h   [Mrows * Dm];
__device__ float  g_qkv [Mrows * QKV3];
__device__ __half g_ctx [Mrows * Dm];
__device__ float  g_x1  [Mrows * Dm];
__device__ __half g_h2  [Mrows * Dm];
__device__ __half g_ff  [Mrows * Dff];
__device__ __half g_wqkv[QKV3 * Dm];    // [n][k] halves
__device__ __half g_wo  [Dm * Dm];      // [n][k]
__device__ __half g_w1  [Dff * Dm];     // [n][k]
__device__ __half g_w2  [Dm * Dff];     // [n][k]
__device__ float  g_bqkv[QKV3];

// ---------------- helpers ---------------------------------------------------
__device__ __forceinline__ uint32_t smem_u32(const void* p) {
    uint32_t a;
    asm("{ .reg .u64 t; cvta.to.shared.u64 t, %1; cvt.u32.u64 %0, t; }"
        : "=r"(a) : "l"(p));
    return a;
}
__device__ __forceinline__ void cpa16(uint32_t dst, const void* src) {
    asm volatile("cp.async.cg.shared.global [%0], [%1], 16;" :: "r"(dst), "l"(src));
}
__device__ __forceinline__ float gelu_exact(float x) {
    return 0.5f * x * (1.0f + erff(x * 0.70710678118654752f));
}
__device__ __forceinline__ void ldsm4(uint32_t addr, uint32_t& r0, uint32_t& r1,
                                      uint32_t& r2, uint32_t& r3) {
    asm volatile("ldmatrix.sync.aligned.m8n8.x4.shared.b16 {%0,%1,%2,%3}, [%4];"
                 : "=r"(r0), "=r"(r1), "=r"(r2), "=r"(r3) : "r"(addr));
}

// ---------------- weight prep: W[k][n] f32 -> Wh[rowOff+n][k] half ----------
__global__ __launch_bounds__(256) void wtrans(
    const float* __restrict__ W, __half* __restrict__ Wh,
    int K, int N, int rowOff)
{
    __shared__ __half t[32][33];
    const int nb = blockIdx.x * 32, kb = blockIdx.y * 32;
    const int tx = threadIdx.x & 31, ty = threadIdx.x >> 5;
    #pragma unroll
    for (int i = 0; i < 32; i += 8)
        t[ty + i][tx] = __float2half(W[(size_t)(kb + ty + i) * N + nb + tx]);
    __syncthreads();
    #pragma unroll
    for (int i = 0; i < 32; i += 8)
        Wh[(size_t)(rowOff + nb + ty + i) * K + kb + tx] = t[tx][ty + i];
}

__global__ __launch_bounds__(256) void bprep(
    const float* __restrict__ bq, const float* __restrict__ bk,
    const float* __restrict__ bv, float* __restrict__ dst)
{
    const int i = blockIdx.x * 256 + threadIdx.x;
    if (i >= QKV3) return;
    dst[i] = (i < Dm) ? bq[i] : (i < 2 * Dm) ? bk[i - Dm] : bv[i - 2 * Dm];
}

// ---------------- fp16 mma.sync GEMM ----------------------------------------
// C[M,N] = A[M,K](half,[m][k]) @ B(half,[n][k]) ; bias/res fp32.
// EPI: 0 = +bias -> float ; 1 = +bias,gelu -> HALF ; 2 = +bias,+res -> float
#define AST   40                          // halves per smem row (80 B)
#define OPB   (128 * AST * 2)             // 10240 B per operand per stage
#define STAGE (2 * OPB)                   // 20480 B
#define NSTG  4
#define MMA_SMEM (NSTG * STAGE)           // 81920 B

template<int EPI>
__global__ __launch_bounds__(256, 2) void mma_gemm(
    const __half* __restrict__ A, const __half* __restrict__ B,
    const float* __restrict__ bias, const float* __restrict__ res,
    void* __restrict__ Cv, int M, int N, int K)
{
    extern __shared__ char smem[];
    const uint32_t sbase = smem_u32(smem);
    const int tid = threadIdx.x;
    const int bm  = blockIdx.y * 128;
    const int bn  = blockIdx.x * 128;
    const int NK  = K >> 5;               // 32-half chunks

    // cp.async: thread -> row tid>>1 (0..127), segments (tid&1)*2, +1 (16 B each)
    const int crow = tid >> 1;
    const int cs0  = (tid & 1) * 2;
    const char* Ag = reinterpret_cast<const char*>(A) + (size_t)(bm + crow) * K * 2;
    const char* Bg = reinterpret_cast<const char*>(B) + (size_t)(bn + crow) * K * 2;

    #define ISSUE_CHUNK(kt, st)                                                 \
    {   const uint32_t ab = sbase + (st) * STAGE + crow * 80;                   \
        const char* agp = Ag + (size_t)(kt) * 64;                               \
        cpa16(ab + cs0 * 16,       agp + cs0 * 16);                             \
        cpa16(ab + (cs0 + 1) * 16, agp + (cs0 + 1) * 16);                       \
        const uint32_t bb = ab + OPB;                                           \
        const char* bgp = Bg + (size_t)(kt) * 64;                               \
        cpa16(bb + cs0 * 16,       bgp + cs0 * 16);                             \
        cpa16(bb + (cs0 + 1) * 16, bgp + (cs0 + 1) * 16);                       \
        asm volatile("cp.async.commit_group;" ::: "memory");                    \
    }

    const int w    = tid >> 5, lane = tid & 31;
    const int wm   = (w >> 2) * 64;
    const int wn   = (w & 3) * 32;
    const int lt   = lane >> 3;           // ldmatrix tile id 0..3
    const int lrow = lane & 7;            // row within tile

    float acc[4][4][4];
    #pragma unroll
    for (int i = 0; i < 4; i++)
        #pragma unroll
        for (int j = 0; j < 4; j++)
            #pragma unroll
            for (int c = 0; c < 4; c++) acc[i][j][c] = 0.f;

    ISSUE_CHUNK(0, 0);
    ISSUE_CHUNK(1, 1);
    ISSUE_CHUNK(2, 2);

    for (int kt = 0; kt < NK; kt++) {
        const int st = kt & (NSTG - 1);
        asm volatile("cp.async.wait_group 2;" ::: "memory");
        __syncthreads();
        if (kt + 3 < NK) {
            ISSUE_CHUNK(kt + 3, (kt + 3) & (NSTG - 1));
        } else {
            asm volatile("cp.async.commit_group;" ::: "memory");
        }

        const uint32_t as = sbase + st * STAGE;
        const uint32_t bs = as + OPB;

        #pragma unroll
        for (int ks = 0; ks < 2; ks++) {
            // A frags: tiles t0(m0-7,k0-7) t1(m8-15,k0-7) t2(m0-7,k8-15) t3(m8-15,k8-15)
            uint32_t a[4][4];
            #pragma unroll
            for (int i = 0; i < 4; i++) {
                const uint32_t addr = as
                    + (uint32_t)(wm + i * 16 + (lt & 1) * 8 + lrow) * 80
                    + ks * 32 + (lt >> 1) * 16;
                ldsm4(addr, a[i][0], a[i][1], a[i][2], a[i][3]);
            }
            // B frags: per pair jp: t0(n0-7,k0-7)=b[2jp][0] t1(n0-7,k8-15)=b[2jp][1]
            //                       t2(n8-15,k0-7)=b[2jp+1][0] t3(n8-15,k8-15)
            uint32_t b[4][2];
            #pragma unroll
            for (int jp = 0; jp < 2; jp++) {
                const uint32_t addr = bs
                    + (uint32_t)(wn + jp * 16 + (lt >> 1) * 8 + lrow) * 80
                    + ks * 32 + (lt & 1) * 16;
                ldsm4(addr, b[2 * jp][0], b[2 * jp][1],
                            b[2 * jp + 1][0], b[2 * jp + 1][1]);
            }
            #pragma unroll
            for (int i = 0; i < 4; i++)
                #pragma unroll
                for (int j = 0; j < 4; j++)
                    asm volatile(
                        "mma.sync.aligned.m16n8k16.row.col.f32.f16.f16.f32 "
                        "{%0,%1,%2,%3}, {%4,%5,%6,%7}, {%8,%9}, {%0,%1,%2,%3};"
                        : "+f"(acc[i][j][0]), "+f"(acc[i][j][1]),
                          "+f"(acc[i][j][2]), "+f"(acc[i][j][3])
                        : "r"(a[i][0]), "r"(a[i][1]), "r"(a[i][2]), "r"(a[i][3]),
                          "r"(b[j][0]), "r"(b[j][1]));
        }
    }
    #undef ISSUE_CHUNK

    // epilogue: C layout per frag: c0/c1 -> (row, col/col+1); c2/c3 -> row+8
    const int lr = lane >> 2;
    const int lk = lane & 3;
    #pragma unroll
    for (int i = 0; i < 4; i++) {
        #pragma unroll
        for (int j = 0; j < 4; j++) {
            const int row0 = bm + wm + i * 16 + lr;
            const int col  = bn + wn + j * 8 + lk * 2;
            #pragma unroll
            for (int hrow = 0; hrow < 2; hrow++) {
                const int row = row0 + hrow * 8;
                float ox = acc[i][j][hrow * 2 + 0] + bias[col + 0];
                float oy = acc[i][j][hrow * 2 + 1] + bias[col + 1];
                if (EPI == 1) {
                    ox = gelu_exact(ox); oy = gelu_exact(oy);
                    __half2* dst = reinterpret_cast<__half2*>(
                        reinterpret_cast<__half*>(Cv) + (size_t)row * N + col);
                    *dst = __floats2half2_rn(ox, oy);
                } else {
                    if (EPI == 2) {
                        const float2 r2 = *reinterpret_cast<const float2*>(
                            res + (size_t)row * N + col);
                        ox += r2.x; oy += r2.y;
                    }
                    float2 o; o.x = ox; o.y = oy;
                    *reinterpret_cast<float2*>(
                        reinterpret_cast<float*>(Cv) + (size_t)row * N + col) = o;
                }
            }
        }
    }
}

// ---------------- LayerNorm (half output) -----------------------------------
__global__ __launch_bounds__(256) void ln_kernel(
    const float* __restrict__ x, const float* __restrict__ g,
    const float* __restrict__ b, __half* __restrict__ out)
{
    const int row = blockIdx.x;
    const int t   = threadIdx.x;
    const float4 v = reinterpret_cast<const float4*>(x + (size_t)row * Dm)[t];

    float s  = v.x + v.y + v.z + v.w;
    float s2 = v.x * v.x + v.y * v.y + v.z * v.z + v.w * v.w;

    __shared__ float red[16];
    #pragma unroll
    for (int o = 16; o; o >>= 1) {
        s  += __shfl_xor_sync(0xffffffffu, s,  o);
        s2 += __shfl_xor_sync(0xffffffffu, s2, o);
    }
    const int w = t >> 5, l = t & 31;
    if (l == 0) { red[w] = s; red[w + 8] = s2; }
    __syncthreads();
    if (w == 0) {
        float a  = (l < 8) ? red[l]     : 0.f;
        float a2 = (l < 8) ? red[l + 8] : 0.f;
        #pragma unroll
        for (int o = 4; o; o >>= 1) {
            a  += __shfl_xor_sync(0xffffffffu, a,  o);
            a2 += __shfl_xor_sync(0xffffffffu, a2, o);
        }
        if (l == 0) { red[0] = a; red[1] = a2; }
    }
    __syncthreads();

    const float mean = red[0] * (1.f / Dm);
    const float var  = red[1] * (1.f / Dm) - mean * mean;
    const float rs   = rsqrtf(var + 1e-5f);

    const float4 gg = reinterpret_cast<const float4*>(g)[t];
    const float4 bb = reinterpret_cast<const float4*>(b)[t];
    const float o0 = (v.x - mean) * rs * gg.x + bb.x;
    const float o1 = (v.y - mean) * rs * gg.y + bb.y;
    const float o2 = (v.z - mean) * rs * gg.z + bb.z;
    const float o3 = (v.w - mean) * rs * gg.w + bb.w;

    __half2* dst = reinterpret_cast<__half2*>(out + (size_t)row * Dm) + t * 2;
    dst[0] = __floats2half2_rn(o0, o1);
    dst[1] = __floats2half2_rn(o2, o3);
}

// ---------------- block-sparse flash attention (packed qkv, half ctx) -------
#define SPAD 130

__global__ __launch_bounds__(256) void attn_kernel(
    const float* __restrict__ qkv, const int* __restrict__ layout,
    __half* __restrict__ ctx)
{
    extern __shared__ float sm[];
    float* sKV  = sm;
    float* sS   = sm + 128 * 64;
    float* sRed = sS + 128 * SPAD;

    const int ib  = blockIdx.x;
    const int hh  = blockIdx.y;
    const int bb  = blockIdx.z;
    const int tid = threadIdx.x;
    const int r    = tid >> 1;
    const int half = tid & 1;

    const size_t qbase = ((size_t)(bb * Sseq + ib * BLKs)) * QKV3 + hh * DHd;
    const float* kptr = qkv + Dm;
    const float* vptr = qkv + 2 * Dm;

    #pragma unroll
    for (int f = tid; f < 2048; f += 256) {
        const int row = f >> 4, c = (f & 15) << 2;
        *reinterpret_cast<float4*>(sKV + row * 64 + c) =
            *reinterpret_cast<const float4*>(qkv + qbase + (size_t)row * QKV3 + c);
    }
    __syncthreads();
    float qreg[64];
    #pragma unroll
    for (int c = 0; c < 64; c += 4)
        *reinterpret_cast<float4*>(qreg + c) = *reinterpret_cast<float4*>(sKV + r * 64 + c);

    float m = -1e30f, l = 0.f;
    float cacc[32];
    #pragma unroll
    for (int d = 0; d < 32; d++) cacc[d] = 0.f;
    const float scale = 0.125f;

    for (int j = 0; j <= ib; j++) {
        if (!layout[(hh * NBl + ib) * NBl + j]) continue;

        __syncthreads();
        const size_t kbase = ((size_t)(bb * Sseq + j * BLKs)) * QKV3 + hh * DHd;
        #pragma unroll
        for (int f = tid; f < 2048; f += 256) {
            const int row = f >> 4, c = (f & 15) << 2;
            *reinterpret_cast<float4*>(sKV + row * 64 + c) =
                *reinterpret_cast<const float4*>(kptr + kbase + (size_t)row * QKV3 + c);
        }
        __syncthreads();

        const int t0 = half * 64;
        float lmax = -1e30f;
        for (int tl = 0; tl < 64; tl++) {
            const int t = t0 + tl;
            float s;
            if (j < ib || t <= r) {
                float dot = 0.f;
                const float* kr = sKV + t * 64;
                #pragma unroll
                for (int d = 0; d < 64; d++) dot = fmaf(qreg[d], kr[d], dot);
                s = dot * scale;
            } else {
                s = -1e9f;
            }
            sS[r * SPAD + half * 65 + tl] = s;
            lmax = fmaxf(lmax, s);
        }
        sRed[r * 2 + half] = lmax;
        __syncthreads();

        #pragma unroll
        for (int f = tid; f < 2048; f += 256) {
            const int row = f >> 4, c = (f & 15) << 2;
            *reinterpret_cast<float4*>(sKV + row * 64 + c) =
                *reinterpret_cast<const float4*>(vptr + kbase + (size_t)row * QKV3 + c);
        }

        const float mb   = fmaxf(sRed[r * 2], sRed[r * 2 + 1]);
        const float mnew = fmaxf(m, mb);
        const float corr = __expf(m - mnew);
        float lsum = 0.f;
        for (int tl = 0; tl < 64; tl++) {
            const int idx = r * SPAD + half * 65 + tl;
            const float p = __expf(sS[idx] - mnew);
            sS[idx] = p;
            lsum += p;
        }
        sRed[256 + r * 2 + half] = lsum;
        __syncthreads();

        l = l * corr + sRed[256 + r * 2] + sRed[256 + r * 2 + 1];
        #pragma unroll
        for (int d = 0; d < 32; d++) cacc[d] *= corr;
        for (int t = 0; t < 128; t++) {
            const float p = sS[r * SPAD + t + (t >> 6)];
            const float* vr = sKV + t * 64 + half * 32;
            #pragma unroll
            for (int d = 0; d < 32; d++) cacc[d] = fmaf(p, vr[d], cacc[d]);
        }
        m = mnew;
    }

    const float inv = 1.f / l;
    __half* dst = ctx + ((size_t)(bb * Sseq + ib * BLKs + r)) * Dm + hh * DHd + half * 32;
    #pragma unroll
    for (int d = 0; d < 32; d += 2)
        *reinterpret_cast<__half2*>(dst + d) =
            __floats2half2_rn(cacc[d] * inv, cacc[d + 1] * inv);
}

#define ATTN_SMEM (128 * 64 * 4 + 128 * SPAD * 4 + 512 * 4)

// ---------------------------------------------------------------------------
extern "C" void kernel_launch(void* const* d_in, const int* in_sizes, int n_in,
                              void* d_out, int out_size)
{
    (void)in_sizes; (void)n_in; (void)out_size;
    const float* x     = (const float*)d_in[0];
    const float* ln1_g = (const float*)d_in[1];
    const float* ln1_b = (const float*)d_in[2];
    const float* Wq    = (const float*)d_in[3];
    const float* bq    = (const float*)d_in[4];
    const float* Wk    = (const float*)d_in[5];
    const float* bk    = (const float*)d_in[6];
    const float* Wv    = (const float*)d_in[7];
    const float* bv    = (const float*)d_in[8];
    const float* Wo    = (const float*)d_in[9];
    const float* bo    = (const float*)d_in[10];
    const float* ln2_g = (const float*)d_in[11];
    const float* ln2_b = (const float*)d_in[12];
    const float* W1    = (const float*)d_in[13];
    const float* b1    = (const float*)d_in[14];
    const float* W2    = (const float*)d_in[15];
    const float* b2    = (const float*)d_in[16];
    const int*   lay   = (const int*)d_in[17];
    float* out = (float*)d_out;

    __half *h, *ctx, *h2, *ff, *wqkv, *wo, *w1, *w2;
    float  *qkv, *x1, *bqkv;
    cudaGetSymbolAddress((void**)&h,    g_h);
    cudaGetSymbolAddress((void**)&qkv,  g_qkv);
    cudaGetSymbolAddress((void**)&ctx,  g_ctx);
    cudaGetSymbolAddress((void**)&x1,   g_x1);
    cudaGetSymbolAddress((void**)&h2,   g_h2);
    cudaGetSymbolAddress((void**)&ff,   g_ff);
    cudaGetSymbolAddress((void**)&wqkv, g_wqkv);
    cudaGetSymbolAddress((void**)&wo,   g_wo);
    cudaGetSymbolAddress((void**)&w1,   g_w1);
    cudaGetSymbolAddress((void**)&w2,   g_w2);
    cudaGetSymbolAddress((void**)&bqkv, g_bqkv);

    cudaFuncSetAttribute(attn_kernel,
                         cudaFuncAttributeMaxDynamicSharedMemorySize, ATTN_SMEM);
    cudaFuncSetAttribute(mma_gemm<0>,
                         cudaFuncAttributeMaxDynamicSharedMemorySize, MMA_SMEM);
    cudaFuncSetAttribute(mma_gemm<1>,
                         cudaFuncAttributeMaxDynamicSharedMemorySize, MMA_SMEM);
    cudaFuncSetAttribute(mma_gemm<2>,
                         cudaFuncAttributeMaxDynamicSharedMemorySize, MMA_SMEM);

    // 0) weight prep: transpose + fp16 (QKV concatenated row blocks)
    wtrans<<<dim3(Dm / 32, Dm / 32), 256>>>(Wq, wqkv, Dm, Dm, 0);
    wtrans<<<dim3(Dm / 32, Dm / 32), 256>>>(Wk, wqkv, Dm, Dm, Dm);
    wtrans<<<dim3(Dm / 32, Dm / 32), 256>>>(Wv, wqkv, Dm, Dm, 2 * Dm);
    wtrans<<<dim3(Dm / 32, Dm / 32), 256>>>(Wo, wo, Dm, Dm, 0);
    wtrans<<<dim3(Dff / 32, Dm / 32), 256>>>(W1, w1, Dm, Dff, 0);
    wtrans<<<dim3(Dm / 32, Dff / 32), 256>>>(W2, w2, Dff, Dm, 0);
    bprep<<<(QKV3 + 255) / 256, 256>>>(bq, bk, bv, bqkv);

    // 1) ln1 -> half h
    ln_kernel<<<Mrows, 256>>>(x, ln1_g, ln1_b, h);

    // 2) fused QKV projection (float out)
    mma_gemm<0><<<dim3(QKV3 / 128, Mrows / 128), 256, MMA_SMEM>>>(
        h, wqkv, bqkv, nullptr, qkv, Mrows, QKV3, Dm);

    // 3) block-sparse attention -> half ctx
    attn_kernel<<<dim3(NBl, Hh, Bsz), 256, ATTN_SMEM>>>(qkv, lay, ctx);

    // 4) output projection + residual (float x1)
    dim3 g1(Dm / 128, Mrows / 128);
    mma_gemm<2><<<g1, 256, MMA_SMEM>>>(ctx, wo, bo, x, x1, Mrows, Dm, Dm);

    // 5) ln2 -> half h2
    ln_kernel<<<Mrows, 256>>>(x1, ln2_g, ln2_b, h2);

    // 6) MLP: gelu -> half ff ; final -> float out
    dim3 g2(Dff / 128, Mrows / 128);
    mma_gemm<1><<<g2, 256, MMA_SMEM>>>(h2, w1, b1, nullptr, ff, Mrows, Dff, Dm);
    mma_gemm<2><<<g1, 256, MMA_SMEM>>>(ff, w2, b2, x1, out, Mrows, Dm, Dff);
}

// round 10
// speedup vs baseline: 3.0529x; 1.7063x over previous
#include <cuda_runtime.h>
#include <cuda_fp16.h>
#include <math.h>
#include <stdint.h>

#define Bsz   2
#define Sseq  2048
#define Dm    1024
#define Hh    16
#define DHd   64
#define BLKs  128
#define NBl   16
#define Mrows (Bsz * Sseq)   // 4096
#define Dff   (4 * Dm)       // 4096
#define QKV3  (3 * Dm)       // 3072

// ---------------- scratch ---------------------------------------------------
__device__ __half g_h   [Mrows * Dm];
__device__ __half g_qkv [Mrows * QKV3];
__device__ __half g_ctx [Mrows * Dm];
__device__ float  g_x1  [Mrows * Dm];
__device__ __half g_h2  [Mrows * Dm];
__device__ __half g_ff  [Mrows * Dff];
__device__ __half g_wqkv[QKV3 * Dm];    // [n][k]
__device__ __half g_wo  [Dm * Dm];
__device__ __half g_w1  [Dff * Dm];
__device__ __half g_w2  [Dm * Dff];
__device__ float  g_bqkv[QKV3];

// ---------------- helpers ---------------------------------------------------
__device__ __forceinline__ uint32_t smem_u32(const void* p) {
    uint32_t a;
    asm("{ .reg .u64 t; cvta.to.shared.u64 t, %1; cvt.u32.u64 %0, t; }"
        : "=r"(a) : "l"(p));
    return a;
}
__device__ __forceinline__ uint32_t h2_as_u32(__half2 h) {
    return *reinterpret_cast<uint32_t*>(&h);
}
__device__ __forceinline__ void cpa16(uint32_t dst, const void* src) {
    asm volatile("cp.async.cg.shared.global [%0], [%1], 16;" :: "r"(dst), "l"(src));
}
__device__ __forceinline__ float gelu_exact(float x) {
    return 0.5f * x * (1.0f + erff(x * 0.70710678118654752f));
}
__device__ __forceinline__ void ldsm4(uint32_t addr, uint32_t& r0, uint32_t& r1,
                                      uint32_t& r2, uint32_t& r3) {
    asm volatile("ldmatrix.sync.aligned.m8n8.x4.shared.b16 {%0,%1,%2,%3}, [%4];"
                 : "=r"(r0), "=r"(r1), "=r"(r2), "=r"(r3) : "r"(addr));
}
__device__ __forceinline__ void ldsm4t(uint32_t addr, uint32_t& r0, uint32_t& r1,
                                       uint32_t& r2, uint32_t& r3) {
    asm volatile("ldmatrix.sync.aligned.m8n8.x4.trans.shared.b16 {%0,%1,%2,%3}, [%4];"
                 : "=r"(r0), "=r"(r1), "=r"(r2), "=r"(r3) : "r"(addr));
}
#define MMA16816(acc, a0, a1, a2, a3, b0, b1)                                   \
    asm volatile("mma.sync.aligned.m16n8k16.row.col.f32.f16.f16.f32 "           \
                 "{%0,%1,%2,%3}, {%4,%5,%6,%7}, {%8,%9}, {%0,%1,%2,%3};"        \
                 : "+f"((acc)[0]), "+f"((acc)[1]), "+f"((acc)[2]), "+f"((acc)[3])\
                 : "r"(a0), "r"(a1), "r"(a2), "r"(a3), "r"(b0), "r"(b1))

// ---------------- weight prep: W[k][n] f32 -> Wh[rowOff+n][k] half ----------
__global__ __launch_bounds__(256) void wtrans(
    const float* __restrict__ W, __half* __restrict__ Wh,
    int K, int N, int rowOff)
{
    __shared__ __half t[32][33];
    const int nb = blockIdx.x * 32, kb = blockIdx.y * 32;
    const int tx = threadIdx.x & 31, ty = threadIdx.x >> 5;
    #pragma unroll
    for (int i = 0; i < 32; i += 8)
        t[ty + i][tx] = __float2half(W[(size_t)(kb + ty + i) * N + nb + tx]);
    __syncthreads();
    #pragma unroll
    for (int i = 0; i < 32; i += 8)
        Wh[(size_t)(rowOff + nb + ty + i) * K + kb + tx] = t[tx][ty + i];
}

__global__ __launch_bounds__(256) void bprep(
    const float* __restrict__ bq, const float* __restrict__ bk,
    const float* __restrict__ bv, float* __restrict__ dst)
{
    const int i = blockIdx.x * 256 + threadIdx.x;
    if (i >= QKV3) return;
    dst[i] = (i < Dm) ? bq[i] : (i < 2 * Dm) ? bk[i - Dm] : bv[i - 2 * Dm];
}

// ---------------- fp16 mma.sync GEMM ----------------------------------------
// EPI: 0=+bias->f32 ; 1=+bias,gelu->half ; 2=+bias,+res->f32 ; 3=+bias->half
#define AST   40
#define OPB   (128 * AST * 2)
#define STAGE (2 * OPB)
#define NSTG  4
#define MMA_SMEM (NSTG * STAGE)

template<int EPI>
__global__ __launch_bounds__(256, 2) void mma_gemm(
    const __half* __restrict__ A, const __half* __restrict__ B,
    const float* __restrict__ bias, const float* __restrict__ res,
    void* __restrict__ Cv, int M, int N, int K)
{
    extern __shared__ char smem[];
    const uint32_t sbase = smem_u32(smem);
    const int tid = threadIdx.x;
    const int bm  = blockIdx.y * 128;
    const int bn  = blockIdx.x * 128;
    const int NK  = K >> 5;

    const int crow = tid >> 1;
    const int cs0  = (tid & 1) * 2;
    const char* Ag = reinterpret_cast<const char*>(A) + (size_t)(bm + crow) * K * 2;
    const char* Bg = reinterpret_cast<const char*>(B) + (size_t)(bn + crow) * K * 2;

    #define ISSUE_CHUNK(kt, st)                                                 \
    {   const uint32_t ab = sbase + (st) * STAGE + crow * 80;                   \
        const char* agp = Ag + (size_t)(kt) * 64;                               \
        cpa16(ab + cs0 * 16,       agp + cs0 * 16);                             \
        cpa16(ab + (cs0 + 1) * 16, agp + (cs0 + 1) * 16);                       \
        const uint32_t bb = ab + OPB;                                           \
        const char* bgp = Bg + (size_t)(kt) * 64;                               \
        cpa16(bb + cs0 * 16,       bgp + cs0 * 16);                             \
        cpa16(bb + (cs0 + 1) * 16, bgp + (cs0 + 1) * 16);                       \
        asm volatile("cp.async.commit_group;" ::: "memory");                    \
    }

    const int w    = tid >> 5, lane = tid & 31;
    const int wm   = (w >> 2) * 64;
    const int wn   = (w & 3) * 32;
    const int lt   = lane >> 3;
    const int lrow = lane & 7;

    float acc[4][4][4];
    #pragma unroll
    for (int i = 0; i < 4; i++)
        #pragma unroll
        for (int j = 0; j < 4; j++)
            #pragma unroll
            for (int c = 0; c < 4; c++) acc[i][j][c] = 0.f;

    ISSUE_CHUNK(0, 0);
    ISSUE_CHUNK(1, 1);
    ISSUE_CHUNK(2, 2);

    for (int kt = 0; kt < NK; kt++) {
        const int st = kt & (NSTG - 1);
        asm volatile("cp.async.wait_group 2;" ::: "memory");
        __syncthreads();
        if (kt + 3 < NK) {
            ISSUE_CHUNK(kt + 3, (kt + 3) & (NSTG - 1));
        } else {
            asm volatile("cp.async.commit_group;" ::: "memory");
        }

        const uint32_t as = sbase + st * STAGE;
        const uint32_t bs = as + OPB;

        #pragma unroll
        for (int ks = 0; ks < 2; ks++) {
            uint32_t a[4][4];
            #pragma unroll
            for (int i = 0; i < 4; i++) {
                const uint32_t addr = as
                    + (uint32_t)(wm + i * 16 + (lt & 1) * 8 + lrow) * 80
                    + ks * 32 + (lt >> 1) * 16;
                ldsm4(addr, a[i][0], a[i][1], a[i][2], a[i][3]);
            }
            uint32_t b[4][2];
            #pragma unroll
            for (int jp = 0; jp < 2; jp++) {
                const uint32_t addr = bs
                    + (uint32_t)(wn + jp * 16 + (lt >> 1) * 8 + lrow) * 80
                    + ks * 32 + (lt & 1) * 16;
                ldsm4(addr, b[2 * jp][0], b[2 * jp][1],
                            b[2 * jp + 1][0], b[2 * jp + 1][1]);
            }
            #pragma unroll
            for (int i = 0; i < 4; i++)
                #pragma unroll
                for (int j = 0; j < 4; j++)
                    MMA16816(acc[i][j], a[i][0], a[i][1], a[i][2], a[i][3],
                             b[j][0], b[j][1]);
        }
    }
    #undef ISSUE_CHUNK

    const int lr = lane >> 2;
    const int lk = lane & 3;
    #pragma unroll
    for (int i = 0; i < 4; i++) {
        #pragma unroll
        for (int j = 0; j < 4; j++) {
            const int row0 = bm + wm + i * 16 + lr;
            const int col  = bn + wn + j * 8 + lk * 2;
            #pragma unroll
            for (int hrow = 0; hrow < 2; hrow++) {
                const int row = row0 + hrow * 8;
                float ox = acc[i][j][hrow * 2 + 0] + bias[col + 0];
                float oy = acc[i][j][hrow * 2 + 1] + bias[col + 1];
                if (EPI == 1 || EPI == 3) {
                    if (EPI == 1) { ox = gelu_exact(ox); oy = gelu_exact(oy); }
                    __half2* dst = reinterpret_cast<__half2*>(
                        reinterpret_cast<__half*>(Cv) + (size_t)row * N + col);
                    *dst = __floats2half2_rn(ox, oy);
                } else {
                    if (EPI == 2) {
                        const float2 r2 = *reinterpret_cast<const float2*>(
                            res + (size_t)row * N + col);
                        ox += r2.x; oy += r2.y;
                    }
                    float2 o; o.x = ox; o.y = oy;
                    *reinterpret_cast<float2*>(
                        reinterpret_cast<float*>(Cv) + (size_t)row * N + col) = o;
                }
            }
        }
    }
}

// ---------------- LayerNorm (half output) -----------------------------------
__global__ __launch_bounds__(256) void ln_kernel(
    const float* __restrict__ x, const float* __restrict__ g,
    const float* __restrict__ b, __half* __restrict__ out)
{
    const int row = blockIdx.x;
    const int t   = threadIdx.x;
    const float4 v = reinterpret_cast<const float4*>(x + (size_t)row * Dm)[t];

    float s  = v.x + v.y + v.z + v.w;
    float s2 = v.x * v.x + v.y * v.y + v.z * v.z + v.w * v.w;

    __shared__ float red[16];
    #pragma unroll
    for (int o = 16; o; o >>= 1) {
        s  += __shfl_xor_sync(0xffffffffu, s,  o);
        s2 += __shfl_xor_sync(0xffffffffu, s2, o);
    }
    const int w = t >> 5, l = t & 31;
    if (l == 0) { red[w] = s; red[w + 8] = s2; }
    __syncthreads();
    if (w == 0) {
        float a  = (l < 8) ? red[l]     : 0.f;
        float a2 = (l < 8) ? red[l + 8] : 0.f;
        #pragma unroll
        for (int o = 4; o; o >>= 1) {
            a  += __shfl_xor_sync(0xffffffffu, a,  o);
            a2 += __shfl_xor_sync(0xffffffffu, a2, o);
        }
        if (l == 0) { red[0] = a; red[1] = a2; }
    }
    __syncthreads();

    const float mean = red[0] * (1.f / Dm);
    const float var  = red[1] * (1.f / Dm) - mean * mean;
    const float rs   = rsqrtf(var + 1e-5f);

    const float4 gg = reinterpret_cast<const float4*>(g)[t];
    const float4 bb = reinterpret_cast<const float4*>(b)[t];
    const float o0 = (v.x - mean) * rs * gg.x + bb.x;
    const float o1 = (v.y - mean) * rs * gg.y + bb.y;
    const float o2 = (v.z - mean) * rs * gg.z + bb.z;
    const float o3 = (v.w - mean) * rs * gg.w + bb.w;

    __half2* dst = reinterpret_cast<__half2*>(out + (size_t)row * Dm) + t * 2;
    dst[0] = __floats2half2_rn(o0, o1);
    dst[1] = __floats2half2_rn(o2, o3);
}

// ---------------- tensor-core block-sparse flash attention ------------------
// CTA (ib, hh, bb), 256 thr (8 warps x 16 q-rows). qkv half packed [row][3072].
#define QST 72   // smem row stride in halves (144 B)
#define ATTN_SMEM (3 * 128 * QST * 2)   // Q, K, V tiles = 55296 B

__global__ __launch_bounds__(256) void attn_kernel(
    const __half* __restrict__ qkv, const int* __restrict__ layout,
    __half* __restrict__ ctx)
{
    extern __shared__ __half smh[];
    __half* sQ = smh;
    __half* sK = smh + 128 * QST;
    __half* sV = smh + 256 * QST;
    const uint32_t sQa = smem_u32(sQ);
    const uint32_t sKa = smem_u32(sK);
    const uint32_t sVa = smem_u32(sV);

    const int ib  = blockIdx.x;
    const int hh  = blockIdx.y;
    const int bb  = blockIdx.z;
    const int tid = threadIdx.x;
    const int w    = tid >> 5, lane = tid & 31;
    const int lr   = lane >> 2, lk = lane & 3;
    const int lt   = lane >> 3, lrow = lane & 7;
    const int wm   = w * 16;

    const size_t qrow0 = (size_t)(bb * Sseq + ib * BLKs);

    // load Q tile [128][64] halves
    for (int f = tid; f < 1024; f += 256) {
        const int row = f >> 3, seg = f & 7;
        *reinterpret_cast<uint4*>(sQ + row * QST + seg * 8) =
            *reinterpret_cast<const uint4*>(qkv + (qrow0 + row) * QKV3 + hh * 64 + seg * 8);
    }
    __syncthreads();

    // Q frags (held in regs for all blocks)
    uint32_t qf[4][4];
    #pragma unroll
    for (int ks = 0; ks < 4; ks++) {
        const uint32_t addr = sQa + (uint32_t)(wm + (lt & 1) * 8 + lrow) * 144
                            + ks * 32 + (lt >> 1) * 16;
        ldsm4(addr, qf[ks][0], qf[ks][1], qf[ks][2], qf[ks][3]);
    }

    float m0 = -1e30f, m1 = -1e30f, l0 = 0.f, l1 = 0.f;
    float octx[8][4];
    #pragma unroll
    for (int jn = 0; jn < 8; jn++)
        #pragma unroll
        for (int c = 0; c < 4; c++) octx[jn][c] = 0.f;

    for (int j = 0; j <= ib; j++) {
        if (!layout[(hh * NBl + ib) * NBl + j]) continue;

        __syncthreads();   // protect prior sK/sV use
        const size_t krow0 = (size_t)(bb * Sseq + j * BLKs);
        for (int f = tid; f < 1024; f += 256) {
            const int row = f >> 3, seg = f & 7;
            const __half* src = qkv + (krow0 + row) * QKV3 + hh * 64 + seg * 8;
            *reinterpret_cast<uint4*>(sK + row * QST + seg * 8) =
                *reinterpret_cast<const uint4*>(src + Dm);
            *reinterpret_cast<uint4*>(sV + row * QST + seg * 8) =
                *reinterpret_cast<const uint4*>(src + 2 * Dm);
        }
        __syncthreads();

        // S = Q K^T  (warp: 16 q-rows x 128 keys)
        float sacc[16][4];
        #pragma unroll
        for (int jf = 0; jf < 16; jf++)
            #pragma unroll
            for (int c = 0; c < 4; c++) sacc[jf][c] = 0.f;

        #pragma unroll
        for (int ks = 0; ks < 4; ks++) {
            #pragma unroll
            for (int jp = 0; jp < 8; jp++) {
                uint32_t b0, b1, b2, b3;
                const uint32_t addr = sKa
                    + (uint32_t)(jp * 16 + (lt >> 1) * 8 + lrow) * 144
                    + ks * 32 + (lt & 1) * 16;
                ldsm4(addr, b0, b1, b2, b3);
                MMA16816(sacc[2 * jp],     qf[ks][0], qf[ks][1], qf[ks][2], qf[ks][3], b0, b1);
                MMA16816(sacc[2 * jp + 1], qf[ks][0], qf[ks][1], qf[ks][2], qf[ks][3], b2, b3);
            }
        }

        // scale + causal mask (diagonal block only)
        const int r0 = wm + lr, r1 = wm + lr + 8;
        #pragma unroll
        for (int jf = 0; jf < 16; jf++) {
            #pragma unroll
            for (int c = 0; c < 4; c++) sacc[jf][c] *= 0.125f;
            if (j == ib) {
                const int c0 = jf * 8 + lk * 2, c1 = c0 + 1;
                if (c0 > r0) sacc[jf][0] = -1e9f;
                if (c1 > r0) sacc[jf][1] = -1e9f;
                if (c0 > r1) sacc[jf][2] = -1e9f;
                if (c1 > r1) sacc[jf][3] = -1e9f;
            }
        }

        // row max (4-lane spread -> shfl reduce)
        float bm0 = -1e30f, bm1 = -1e30f;
        #pragma unroll
        for (int jf = 0; jf < 16; jf++) {
            bm0 = fmaxf(bm0, fmaxf(sacc[jf][0], sacc[jf][1]));
            bm1 = fmaxf(bm1, fmaxf(sacc[jf][2], sacc[jf][3]));
        }
        bm0 = fmaxf(bm0, __shfl_xor_sync(0xffffffffu, bm0, 1));
        bm0 = fmaxf(bm0, __shfl_xor_sync(0xffffffffu, bm0, 2));
        bm1 = fmaxf(bm1, __shfl_xor_sync(0xffffffffu, bm1, 1));
        bm1 = fmaxf(bm1, __shfl_xor_sync(0xffffffffu, bm1, 2));

        const float nm0 = fmaxf(m0, bm0), nm1 = fmaxf(m1, bm1);
        const float cr0 = __expf(m0 - nm0), cr1 = __expf(m1 - nm1);

        float s0 = 0.f, s1 = 0.f;
        uint32_t ph[16][2];
        #pragma unroll
        for (int jf = 0; jf < 16; jf++) {
            const float p00 = __expf(sacc[jf][0] - nm0);
            const float p01 = __expf(sacc[jf][1] - nm0);
            const float p10 = __expf(sacc[jf][2] - nm1);
            const float p11 = __expf(sacc[jf][3] - nm1);
            s0 += p00 + p01; s1 += p10 + p11;
            ph[jf][0] = h2_as_u32(__floats2half2_rn(p00, p01));
            ph[jf][1] = h2_as_u32(__floats2half2_rn(p10, p11));
        }
        s0 += __shfl_xor_sync(0xffffffffu, s0, 1);
        s0 += __shfl_xor_sync(0xffffffffu, s0, 2);
        s1 += __shfl_xor_sync(0xffffffffu, s1, 1);
        s1 += __shfl_xor_sync(0xffffffffu, s1, 2);

        l0 = l0 * cr0 + s0;
        l1 = l1 * cr1 + s1;
        #pragma unroll
        for (int jn = 0; jn < 8; jn++) {
            octx[jn][0] *= cr0; octx[jn][1] *= cr0;
            octx[jn][2] *= cr1; octx[jn][3] *= cr1;
        }

        // ctx += P V   (V^T B-frags via ldmatrix.trans)
        #pragma unroll
        for (int kk = 0; kk < 8; kk++) {
            const uint32_t a0 = ph[2 * kk][0],     a1 = ph[2 * kk][1];
            const uint32_t a2 = ph[2 * kk + 1][0], a3 = ph[2 * kk + 1][1];
            #pragma unroll
            for (int jp = 0; jp < 4; jp++) {
                uint32_t b0, b1, b2, b3;
                const uint32_t addr = sVa
                    + (uint32_t)(kk * 16 + (lt & 1) * 8 + lrow) * 144
                    + (uint32_t)(jp * 16 + (lt >> 1) * 8) * 2;
                ldsm4t(addr, b0, b1, b2, b3);
                MMA16816(octx[2 * jp],     a0, a1, a2, a3, b0, b1);
                MMA16816(octx[2 * jp + 1], a0, a1, a2, a3, b2, b3);
            }
        }
        m0 = nm0; m1 = nm1;
    }

    const float inv0 = 1.f / l0, inv1 = 1.f / l1;
    __half* base0 = ctx + (qrow0 + wm + lr) * Dm + hh * 64;
    __half* base1 = ctx + (qrow0 + wm + lr + 8) * Dm + hh * 64;
    #pragma unroll
    for (int jn = 0; jn < 8; jn++) {
        const int col = jn * 8 + lk * 2;
        *reinterpret_cast<__half2*>(base0 + col) =
            __floats2half2_rn(octx[jn][0] * inv0, octx[jn][1] * inv0);
        *reinterpret_cast<__half2*>(base1 + col) =
            __floats2half2_rn(octx[jn][2] * inv1, octx[jn][3] * inv1);
    }
}

// ---------------------------------------------------------------------------
extern "C" void kernel_launch(void* const* d_in, const int* in_sizes, int n_in,
                              void* d_out, int out_size)
{
    (void)in_sizes; (void)n_in; (void)out_size;
    const float* x     = (const float*)d_in[0];
    const float* ln1_g = (const float*)d_in[1];
    const float* ln1_b = (const float*)d_in[2];
    const float* Wq    = (const float*)d_in[3];
    const float* bq    = (const float*)d_in[4];
    const float* Wk    = (const float*)d_in[5];
    const float* bk    = (const float*)d_in[6];
    const float* Wv    = (const float*)d_in[7];
    const float* bv    = (const float*)d_in[8];
    const float* Wo    = (const float*)d_in[9];
    const float* bo    = (const float*)d_in[10];
    const float* ln2_g = (const float*)d_in[11];
    const float* ln2_b = (const float*)d_in[12];
    const float* W1    = (const float*)d_in[13];
    const float* b1    = (const float*)d_in[14];
    const float* W2    = (const float*)d_in[15];
    const float* b2    = (const float*)d_in[16];
    const int*   lay   = (const int*)d_in[17];
    float* out = (float*)d_out;

    __half *h, *qkv, *ctx, *h2, *ff, *wqkv, *wo, *w1, *w2;
    float  *x1, *bqkv;
    cudaGetSymbolAddress((void**)&h,    g_h);
    cudaGetSymbolAddress((void**)&qkv,  g_qkv);
    cudaGetSymbolAddress((void**)&ctx,  g_ctx);
    cudaGetSymbolAddress((void**)&x1,   g_x1);
    cudaGetSymbolAddress((void**)&h2,   g_h2);
    cudaGetSymbolAddress((void**)&ff,   g_ff);
    cudaGetSymbolAddress((void**)&wqkv, g_wqkv);
    cudaGetSymbolAddress((void**)&wo,   g_wo);
    cudaGetSymbolAddress((void**)&w1,   g_w1);
    cudaGetSymbolAddress((void**)&w2,   g_w2);
    cudaGetSymbolAddress((void**)&bqkv, g_bqkv);

    cudaFuncSetAttribute(attn_kernel,
                         cudaFuncAttributeMaxDynamicSharedMemorySize, ATTN_SMEM);
    cudaFuncSetAttribute(mma_gemm<1>,
                         cudaFuncAttributeMaxDynamicSharedMemorySize, MMA_SMEM);
    cudaFuncSetAttribute(mma_gemm<2>,
                         cudaFuncAttributeMaxDynamicSharedMemorySize, MMA_SMEM);
    cudaFuncSetAttribute(mma_gemm<3>,
                         cudaFuncAttributeMaxDynamicSharedMemorySize, MMA_SMEM);

    // 0) weight prep
    wtrans<<<dim3(Dm / 32, Dm / 32), 256>>>(Wq, wqkv, Dm, Dm, 0);
    wtrans<<<dim3(Dm / 32, Dm / 32), 256>>>(Wk, wqkv, Dm, Dm, Dm);
    wtrans<<<dim3(Dm / 32, Dm / 32), 256>>>(Wv, wqkv, Dm, Dm, 2 * Dm);
    wtrans<<<dim3(Dm / 32, Dm / 32), 256>>>(Wo, wo, Dm, Dm, 0);
    wtrans<<<dim3(Dff / 32, Dm / 32), 256>>>(W1, w1, Dm, Dff, 0);
    wtrans<<<dim3(Dm / 32, Dff / 32), 256>>>(W2, w2, Dff, Dm, 0);
    bprep<<<(QKV3 + 255) / 256, 256>>>(bq, bk, bv, bqkv);

    // 1) ln1 -> half h
    ln_kernel<<<Mrows, 256>>>(x, ln1_g, ln1_b, h);

    // 2) fused QKV projection (half out)
    mma_gemm<3><<<dim3(QKV3 / 128, Mrows / 128), 256, MMA_SMEM>>>(
        h, wqkv, bqkv, nullptr, qkv, Mrows, QKV3, Dm);

    // 3) tensor-core block-sparse attention -> half ctx
    attn_kernel<<<dim3(NBl, Hh, Bsz), 256, ATTN_SMEM>>>(qkv, lay, ctx);

    // 4) output projection + residual (float x1)
    dim3 g1(Dm / 128, Mrows / 128);
    mma_gemm<2><<<g1, 256, MMA_SMEM>>>(ctx, wo, bo, x, x1, Mrows, Dm, Dm);

    // 5) ln2 -> half h2
    ln_kernel<<<Mrows, 256>>>(x1, ln2_g, ln2_b, h2);

    // 6) MLP
    dim3 g2(Dff / 128, Mrows / 128);
    mma_gemm<1><<<g2, 256, MMA_SMEM>>>(h2, w1, b1, nullptr, ff, Mrows, Dff, Dm);
    mma_gemm<2><<<g1, 256, MMA_SMEM>>>(ff, w2, b2, x1, out, Mrows, Dm, Dff);
}